// round 14
// baseline (speedup 1.0000x reference)
#include <cuda_runtime.h>
#include <math.h>
#include <stdint.h>

// Problem constants
#define BB   256
#define KIN  8
#define CC   1152
#define JJ   10
#define DD   16
#define JD   160
#define XKC  9216          // KIN*CC

// 8-capsule sub-chunks (fragment granularity & GEMM1 blocks): 144
#define NSUB 144
// GEMM2: 16-capsule chunks (M=128 rows), K=64 batch slice
#define CB2  16
#define NCH2 72

#define SMEMB1 45376       // 2816 uint4 B frags (45056) + cs[80]
#define SMEMB2 45376       // 2816 uint4 B frags + sAg[80]

// ---------------------------------------------------------------------------
// Device globals (runtime allocation forbidden)
// ---------------------------------------------------------------------------
__device__ alignas(16) float g_spart[NSUB * BB * JD];   // split-K partials (23.6MB)
__device__ alignas(16) uint4 g_xf1h[NSUB * 2 * 2048];   // GEMM1 A-frag hi (9.4MB)
__device__ alignas(16) uint4 g_xf1l[NSUB * 2 * 2048];   // GEMM1 A-frag lo
__device__ alignas(16) uint4 g_xf2h[NCH2 * 4 * 2048];   // GEMM2 A-frag hi
__device__ alignas(16) uint4 g_xf2l[NCH2 * 4 * 2048];   // GEMM2 A-frag lo
__device__ alignas(16) float2 g_wf[NSUB * 5120];        // W frag pairs (5.9MB)
__device__ alignas(16) uint4 g_wa[NCH2 * 5120];         // agreement W quads (5.9MB)
__device__ alignas(16) uint4 g_vf[4 * 5120];            // v frags per b-slice (327KB)
__device__ alignas(16) float g_b[CC * JJ];              // routing logits

__device__ __forceinline__ uint32_t tf32r(float f) {
    uint32_t u; asm("cvt.rna.tf32.f32 %0, %1;" : "=r"(u) : "f"(f)); return u;
}
__device__ __forceinline__ void hilo(float v, uint32_t& h, uint32_t& l) {
    h = tf32r(v);
    l = tf32r(v - __uint_as_float(h));
}
__device__ __forceinline__ void mma8(float* d, const uint4& a,
                                     uint32_t b0, uint32_t b1) {
    asm volatile(
        "mma.sync.aligned.m16n8k8.row.col.f32.tf32.tf32.f32 "
        "{%0,%1,%2,%3}, {%4,%5,%6,%7}, {%8,%9}, {%0,%1,%2,%3};"
        : "+f"(d[0]), "+f"(d[1]), "+f"(d[2]), "+f"(d[3])
        : "r"(a.x), "r"(a.y), "r"(a.z), "r"(a.w), "r"(b0), "r"(b1));
}

// ---------------------------------------------------------------------------
// prepAll: all one-time fragment preparation in a single 792-block launch.
// ---------------------------------------------------------------------------
__global__ void __launch_bounds__(256) prepAll(const float* __restrict__ x,
                                               const float* __restrict__ W) {
    int bid = blockIdx.x;
    if (bid < 288) {
        int sub = bid >> 1, half = bid & 1;
        int c0 = sub * 8, b0 = half * 128;
        size_t base = (size_t)bid * 2048;
#pragma unroll
        for (int i = threadIdx.x; i < 2048; i += 256) {
            int w = i >> 8, k8 = (i >> 5) & 7, lane = i & 31;
            int tig = lane & 3, g = lane >> 2;
            int m0 = w * 16 + g;
            const float* xb = x + (size_t)(b0 + m0) * XKC + (2 * tig) * CC + c0 + k8;
            uint4 h, l;
            hilo(xb[0], h.x, l.x);              // A[m0][kc]
            hilo(xb[8 * XKC], h.y, l.y);        // A[m0+8][kc]
            hilo(xb[CC], h.z, l.z);             // A[m0][kc+4] (kin+1)
            hilo(xb[8 * XKC + CC], h.w, l.w);   // A[m0+8][kc+4]
            g_xf1h[base + i] = h;
            g_xf1l[base + i] = l;
        }
    } else if (bid < 576) {
        int idx = bid - 288;
        int chunk = idx >> 2, slice = idx & 3;
        int c0 = chunk * CB2, b0 = slice * 64;
        size_t base = (size_t)idx * 2048;
#pragma unroll
        for (int i = threadIdx.x; i < 2048; i += 256) {
            int w = i >> 8, k8 = (i >> 5) & 7, lane = i & 31;
            int tig = lane & 3, g = lane >> 2;
            int kc = k8 * 8 + tig;
            const float* xb = x + (size_t)(b0 + kc) * XKC + w * CC + c0 + g;
            uint4 h, l;
            hilo(xb[0], h.x, l.x);              // XT[w*16+g][kc]
            hilo(xb[8], h.y, l.y);              // cl = g+8
            hilo(xb[4 * XKC], h.z, l.z);        // kc+4
            hilo(xb[4 * XKC + 8], h.w, l.w);
            g_xf2h[base + i] = h;
            g_xf2l[base + i] = l;
        }
    } else if (bid < 720) {
        int sub = bid - 576;
        int c0 = sub * 8;
        size_t base = (size_t)sub * 5120;
#pragma unroll
        for (int i = threadIdx.x; i < 5120; i += 256) {
            int k8 = i / 640, rem = i - k8 * 640, lane = rem / 20, nt = rem - lane * 20;
            int tig = lane & 3, g = lane >> 2;
            int n = nt * 8 + g;
            g_wf[base + i] = *(const float2*)(
                W + (size_t)(c0 + k8) * 1280 + n * 8 + 2 * tig);
        }
    } else {
        // agreement W quads: g_wa[chunk][(w*20+nt)*32+lane]
        int chunk = bid - 720;
        int c0 = chunk * CB2;
        size_t base = (size_t)chunk * 5120;
#pragma unroll
        for (int i = threadIdx.x; i < 5120; i += 256) {
            int w = i / 640, rem = i - w * 640, nt = rem >> 5, lane = rem & 31;
            int tig = lane & 3, g = lane >> 2;
            int n = nt * 8 + 2 * tig;
            const float* w0 = W + (size_t)(c0 + g) * 1280 + n * 8 + w;
            const float* w1 = W + (size_t)(c0 + g + 8) * 1280 + n * 8 + w;
            uint4 q;
            q.x = __float_as_uint(w0[0]);
            q.y = __float_as_uint(w0[8]);
            q.z = __float_as_uint(w1[0]);
            q.w = __float_as_uint(w1[8]);
            g_wa[base + i] = q;
        }
    }
}

// ---------------------------------------------------------------------------
// MMA pass: M=128 x N=80 x K=64. A streamed from gmem frags (LDG.128),
// B fragments in smem at stride 11 uint4 (conflict-free LDS.128).
// ---------------------------------------------------------------------------
__device__ __forceinline__ void gemm_pass(const uint4* __restrict__ aH,
                                          const uint4* __restrict__ aL,
                                          const uint4* bb4, int tid,
                                          float d[10][4]) {
    int w = tid >> 5, lane = tid & 31;
    const uint4* ah = aH + w * 256 + lane;
    const uint4* al = aL + w * 256 + lane;
#pragma unroll
    for (int k8 = 0; k8 < 8; k8++) {
        uint4 h = ah[k8 * 32];
        uint4 l = al[k8 * 32];
        const uint4* bp = bb4 + (k8 * 32 + lane) * 11;
#pragma unroll
        for (int nt = 0; nt < 10; nt++) {
            uint4 bq = bp[nt];
            mma8(d[nt], h, bq.x, bq.y);   // hi*hi
            mma8(d[nt], h, bq.z, bq.w);   // hi*lo
            mma8(d[nt], l, bq.x, bq.y);   // lo*hi
        }
    }
}

// ---------------------------------------------------------------------------
// Kernel B (GEMM1): grid (144,2,2) = (sub, b-half, n-half); block 256;
// 3 blocks/SM. B = c_ij*W from g_wf; fragment epilogue -> g_spart[sub].
// ---------------------------------------------------------------------------
__global__ void __launch_bounds__(256, 3) kernB() {
    extern __shared__ float sm[];
    uint4* bb4 = (uint4*)sm;            // 2816 uint4 = 45056B
    float* cs = sm + 11264;             // 80 floats

    int tid = threadIdx.x;
    int sub = blockIdx.x, half = blockIdx.y, nh = blockIdx.z;
    int c0 = sub * 8;

    // softmax for 8 capsules
    if (tid < 80) {
        int cl = tid / 10, j = tid - cl * 10;
        const float* br = g_b + (size_t)(c0 + cl) * JJ;
        float bv[JJ], mx = -1e30f;
#pragma unroll
        for (int q = 0; q < JJ; q++) { bv[q] = br[q]; mx = fmaxf(mx, bv[q]); }
        float sum = 0.f;
#pragma unroll
        for (int q = 0; q < JJ; q++) { bv[q] = expf(bv[q] - mx); sum += bv[q]; }
        cs[tid] = bv[j] / sum;
    }
    __syncthreads();

    // B fragments (this n-half): LDG.64 from g_wf, scale, hilo, STS.128
    const float2* wf = g_wf + (size_t)sub * 5120;
#pragma unroll
    for (int i = tid; i < 2560; i += 256) {
        int k8 = i / 320, rem = i - k8 * 320, lane = rem / 10, ntl = rem - lane * 10;
        int g = lane >> 2;
        int ntg = nh * 10 + ntl;
        float sc = cs[k8 * 10 + ((ntg * 8 + g) >> 4)];   // cl = k8, j = n>>4
        float2 wv = wf[k8 * 640 + lane * 20 + ntg];
        uint4 q;
        hilo(sc * wv.x, q.x, q.z);
        hilo(sc * wv.y, q.y, q.w);
        bb4[(k8 * 32 + lane) * 11 + ntl] = q;
    }
    __syncthreads();

    float d[10][4];
#pragma unroll
    for (int nt = 0; nt < 10; nt++)
#pragma unroll
        for (int q = 0; q < 4; q++) d[nt][q] = 0.f;

    const uint4* aH = g_xf1h + ((size_t)sub * 2 + half) * 2048;
    const uint4* aL = g_xf1l + ((size_t)sub * 2 + half) * 2048;
    gemm_pass(aH, aL, bb4, tid, d);

    // direct fragment store
    int w = tid >> 5, lane = tid & 31, g = lane >> 2, tig = lane & 3;
    float* dst = g_spart + ((size_t)sub * BB + half * 128 + w * 16 + g) * JD
               + nh * 80 + 2 * tig;
#pragma unroll
    for (int nt = 0; nt < 10; nt++) {
        *(float2*)(dst + nt * 8) = make_float2(d[nt][0], d[nt][1]);
        *(float2*)(dst + 8 * JD + nt * 8) = make_float2(d[nt][2], d[nt][3]);
    }
}

// ---------------------------------------------------------------------------
// Kernel C: reduce 144 split-K partials + squash; writes v-fragments g_vf
// (and d_out on the final iteration). grid 80, block 512.
// ---------------------------------------------------------------------------
__global__ void __launch_bounds__(512) kernC(float* __restrict__ out) {
    int idx = blockIdx.x * 512 + threadIdx.x;   // b*160 + n
    float s = 1e-5f;                            // ref adds 1e-5 BEFORE magnitudes
    const float* sp = g_spart + idx;
#pragma unroll 8
    for (int ch = 0; ch < NSUB; ch++)
        s += sp[(size_t)ch * (BB * JD)];

    float mag = s * s;
#pragma unroll
    for (int off = 8; off; off >>= 1)
        mag += __shfl_xor_sync(0xffffffffu, mag, off, 16);

    float v = s * (mag / ((1.f + mag) * sqrtf(mag)));

    // scatter v into fragment slots: slice = b>>6, kc = b&63
    int b = idx / JD, n = idx - b * JD;
    int slice = b >> 6, kc = b & 63;
    int k8 = kc >> 3, rr = kc & 7, tig = rr & 3, hf = rr >> 2;
    int lane = (n & 7) * 4 + tig, nt = n >> 3;
    uint32_t h, l;
    hilo(v, h, l);
    uint32_t* vq = (uint32_t*)&g_vf[(size_t)slice * 5120 + (k8 * 32 + lane) * 20 + nt];
    vq[hf] = h;          // .x (kc) or .y (kc+4)
    vq[2 + hf] = l;      // .z or .w

    if (out) out[idx] = v;                      // (B,J,D,1) same linearization
}

// ---------------------------------------------------------------------------
// Kernel D (GEMM2): grid (72,4,2) = (chunk, b-slice, n-half); block 256;
// fragment-space agreement (no G staging, no scattered W reads).
// n-half nh covers j = nh*5 + {0..4} (disjoint atomics across halves).
// ---------------------------------------------------------------------------
__global__ void __launch_bounds__(256, 3) kernD() {
    extern __shared__ float sm[];
    uint4* bb4 = (uint4*)sm;            // 2816 uint4
    float* sAg = sm + 11264;            // 80 floats: agreement[cl][jl]

    int tid = threadIdx.x;
    int chunk = blockIdx.x, slice = blockIdx.y, nh = blockIdx.z;
    int c0 = chunk * CB2;

    if (tid < 80) sAg[tid] = 0.f;

    // B fragments (this n-half): coalesced copy from g_vf
    const uint4* vf = g_vf + (size_t)slice * 5120;
#pragma unroll
    for (int i = tid; i < 2560; i += 256) {
        int k8 = i / 320, rem = i - k8 * 320, lane = rem / 10, ntl = rem - lane * 10;
        bb4[(k8 * 32 + lane) * 11 + ntl] = vf[k8 * 640 + lane * 20 + nh * 10 + ntl];
    }
    __syncthreads();

    float d[10][4];
#pragma unroll
    for (int nt = 0; nt < 10; nt++)
#pragma unroll
        for (int q = 0; q < 4; q++) d[nt][q] = 0.f;

    const uint4* aH = g_xf2h + ((size_t)chunk * 4 + slice) * 2048;
    const uint4* aL = g_xf2l + ((size_t)chunk * 4 + slice) * 2048;
    gemm_pass(aH, aL, bb4, tid, d);

    // fragment-space agreement: d[ntl] holds G rows (kin*16+g, kin*16+g+8),
    // cols n = (nh*10+ntl)*8 + 2tig {,+1}; j = nh*5 + (ntl>>1).
    int w = tid >> 5, lane = tid & 31, g = lane >> 2, tig = lane & 3;
    float ag0[5], ag1[5];
#pragma unroll
    for (int j = 0; j < 5; j++) { ag0[j] = 0.f; ag1[j] = 0.f; }

    const uint4* wap = g_wa + (size_t)chunk * 5120 + w * 640 + nh * 320 + lane;
#pragma unroll
    for (int ntl = 0; ntl < 10; ntl++) {
        uint4 q = wap[ntl * 32];
        float wx = __uint_as_float(q.x), wy = __uint_as_float(q.y);
        float wz = __uint_as_float(q.z), ww = __uint_as_float(q.w);
        int jl = ntl >> 1;
        ag0[jl] = fmaf(wx, d[ntl][0], fmaf(wy, d[ntl][1], ag0[jl]));
        ag1[jl] = fmaf(wz, d[ntl][2], fmaf(ww, d[ntl][3], ag1[jl]));
    }
    // reduce across the 4 tig lanes (same g)
#pragma unroll
    for (int j = 0; j < 5; j++) {
        ag0[j] += __shfl_xor_sync(0xffffffffu, ag0[j], 1, 4);
        ag0[j] += __shfl_xor_sync(0xffffffffu, ag0[j], 2, 4);
        ag1[j] += __shfl_xor_sync(0xffffffffu, ag1[j], 1, 4);
        ag1[j] += __shfl_xor_sync(0xffffffffu, ag1[j], 2, 4);
    }
    if (tig == 0) {
#pragma unroll
        for (int j = 0; j < 5; j++) {
            atomicAdd(&sAg[g * 5 + j], ag0[j]);
            atomicAdd(&sAg[(g + 8) * 5 + j], ag1[j]);
        }
    }
    __syncthreads();

    if (tid < 80) {
        int cl = tid / 5, jl = tid - cl * 5;
        atomicAdd(&g_b[(c0 + cl) * JJ + nh * 5 + jl], sAg[tid]);
    }
}

// ---------------------------------------------------------------------------
// Host launcher (graph-capturable)
// ---------------------------------------------------------------------------
extern "C" void kernel_launch(void* const* d_in, const int* in_sizes, int n_in,
                              void* d_out, int out_size) {
    const float* x = (const float*)d_in[0];
    const float* W = (const float*)d_in[1];
    if (in_sizes[0] != BB * XKC) {   // defensive mapping by element count
        x = (const float*)d_in[1];
        W = (const float*)d_in[0];
    }

    cudaFuncSetAttribute(kernB, cudaFuncAttributeMaxDynamicSharedMemorySize, SMEMB1);
    cudaFuncSetAttribute(kernD, cudaFuncAttributeMaxDynamicSharedMemorySize, SMEMB2);

    void* pb = nullptr;
    cudaGetSymbolAddress(&pb, g_b);
    cudaMemsetAsync(pb, 0, CC * JJ * sizeof(float));   // b_ij = 0 each call

    prepAll<<<792, 256>>>(x, W);                       // all frags, one launch

    dim3 gB(NSUB, 2, 2);    // (144, 2, 2)
    dim3 gD(NCH2, 4, 2);    // (72, 4, 2)
    for (int it = 0; it < 4; it++) {
        kernB<<<gB, 256, SMEMB1>>>();                           // tensor GEMM1
        kernC<<<(BB * JD) / 512, 512>>>(it == 3 ? (float*)d_out : nullptr);
        if (it < 3)                                             // iter-4 agreement dead
            kernD<<<gD, 256, SMEMB2>>>();                       // tensor GEMM2
    }
}

// round 15
// speedup vs baseline: 1.4644x; 1.4644x over previous
#include <cuda_runtime.h>
#include <cuda_bf16.h>
#include <math.h>
#include <stdint.h>

// Problem constants
#define BB   256
#define KIN  8
#define CC   1152
#define JJ   10
#define DD   16
#define JD   160
#define XKC  9216          // KIN*CC

// 8-capsule sub-chunks (fragment granularity & GEMM1 blocks): 144
#define NSUB 144
// GEMM2: 16-capsule chunks (M=128 rows), K=64 batch slice
#define CB2  16
#define NCH2 72

#define SMEMB1 43328       // 2688 uint4 B frags (43008) + cs[80]
#define SMEMB2 43648       // 2688 uint4 B frags + sAg[160]

// ---------------------------------------------------------------------------
// Device globals (runtime allocation forbidden)
// ---------------------------------------------------------------------------
__device__ alignas(16) float g_spart[NSUB * BB * JD];   // split-K partials (23.6MB)
__device__ alignas(16) uint4 g_xf1h[NSUB * 2 * 1024];   // GEMM1 A-frag hi bf16 (4.7MB)
__device__ alignas(16) uint4 g_xf1l[NSUB * 2 * 1024];   // GEMM1 A-frag lo
__device__ alignas(16) uint4 g_xf2h[NCH2 * 4 * 1024];   // GEMM2 A-frag hi
__device__ alignas(16) uint4 g_xf2l[NCH2 * 4 * 1024];   // GEMM2 A-frag lo
__device__ alignas(16) float2 g_wf[NSUB * 5120];        // W frag pairs (5.9MB)
__device__ alignas(16) uint4 g_wa[NCH2 * 5120];         // agreement W quads (5.9MB)
__device__ alignas(16) uint4 g_vf[4 * 2560];            // v bf16 frags per b-slice
__device__ alignas(16) float g_b[CC * JJ];              // routing logits

// bf16 hi/lo split + pack (element with LOWER k index in LOW 16 bits)
__device__ __forceinline__ void bfpackhl(float v0, float v1,
                                         uint32_t& hp, uint32_t& lp) {
    __nv_bfloat16 h0 = __float2bfloat16(v0);
    __nv_bfloat16 h1 = __float2bfloat16(v1);
    __nv_bfloat16 l0 = __float2bfloat16(v0 - __bfloat162float(h0));
    __nv_bfloat16 l1 = __float2bfloat16(v1 - __bfloat162float(h1));
    hp = (uint32_t)__bfloat16_as_ushort(h0) | ((uint32_t)__bfloat16_as_ushort(h1) << 16);
    lp = (uint32_t)__bfloat16_as_ushort(l0) | ((uint32_t)__bfloat16_as_ushort(l1) << 16);
}
__device__ __forceinline__ void bfhilo1(float v, uint16_t& h, uint16_t& l) {
    __nv_bfloat16 bh = __float2bfloat16(v);
    __nv_bfloat16 bl = __float2bfloat16(v - __bfloat162float(bh));
    h = __bfloat16_as_ushort(bh);
    l = __bfloat16_as_ushort(bl);
}
__device__ __forceinline__ void mma16(float* d, const uint4& a,
                                      uint32_t b0, uint32_t b1) {
    asm volatile(
        "mma.sync.aligned.m16n8k16.row.col.f32.bf16.bf16.f32 "
        "{%0,%1,%2,%3}, {%4,%5,%6,%7}, {%8,%9}, {%0,%1,%2,%3};"
        : "+f"(d[0]), "+f"(d[1]), "+f"(d[2]), "+f"(d[3])
        : "r"(a.x), "r"(a.y), "r"(a.z), "r"(a.w), "r"(b0), "r"(b1));
}

// ---------------------------------------------------------------------------
// prepAll: one-time fragment preparation, single 792-block launch.
//   [0,288): GEMM1 A-frags; [288,576): GEMM2 A-frags;
//   [576,720): W frag pairs; [720,792): agreement W quads.
// k16-step mapping GEMM1: k = s*16+klocal; cl = k>>3 (=2s or 2s+1), kin = k&7.
// ---------------------------------------------------------------------------
__global__ void __launch_bounds__(256) prepAll(const float* __restrict__ x,
                                               const float* __restrict__ W) {
    int bid = blockIdx.x;
    if (bid < 288) {
        int sub = bid >> 1, half = bid & 1;
        int c0 = sub * 8, b0 = half * 128;
        size_t base = (size_t)bid * 1024;
#pragma unroll
        for (int i = threadIdx.x; i < 1024; i += 256) {
            int w = i >> 7, s = (i >> 5) & 3, lane = i & 31;
            int tig = lane & 3, g = lane >> 2;
            int m0 = w * 16 + g;
            const float* xb = x + (size_t)(b0 + m0) * XKC + (2 * tig) * CC + c0;
            uint4 h, l;
            bfpackhl(xb[2 * s], xb[CC + 2 * s], h.x, l.x);               // rows m0, cl=2s
            bfpackhl(xb[8 * XKC + 2 * s], xb[8 * XKC + CC + 2 * s], h.y, l.y);
            bfpackhl(xb[2 * s + 1], xb[CC + 2 * s + 1], h.z, l.z);       // cl=2s+1
            bfpackhl(xb[8 * XKC + 2 * s + 1], xb[8 * XKC + CC + 2 * s + 1], h.w, l.w);
            g_xf1h[base + i] = h;
            g_xf1l[base + i] = l;
        }
    } else if (bid < 576) {
        int idx = bid - 288;
        int chunk = idx >> 2, slice = idx & 3;
        int c0 = chunk * CB2, b0 = slice * 64;
        size_t base = (size_t)idx * 1024;
#pragma unroll
        for (int i = threadIdx.x; i < 1024; i += 256) {
            int w = i >> 7, s = (i >> 5) & 3, lane = i & 31;
            int tig = lane & 3, g = lane >> 2;
            const float* xb = x + (size_t)(b0 + s * 16 + 2 * tig) * XKC + w * CC + c0;
            uint4 h, l;
            bfpackhl(xb[g], xb[XKC + g], h.x, l.x);                       // r=w16+g, b pair0
            bfpackhl(xb[g + 8], xb[XKC + g + 8], h.y, l.y);               // r=w16+g+8
            bfpackhl(xb[8 * XKC + g], xb[9 * XKC + g], h.z, l.z);         // b pair1
            bfpackhl(xb[8 * XKC + g + 8], xb[9 * XKC + g + 8], h.w, l.w);
            g_xf2h[base + i] = h;
            g_xf2l[base + i] = l;
        }
    } else if (bid < 720) {
        // W frag pairs: i = ((s*32+lane)*20+nt)*2+p ; value = W[c0+2s+p, n, 2tig..2tig+1]
        int sub = bid - 576;
        int c0 = sub * 8;
        size_t base = (size_t)sub * 5120;
#pragma unroll
        for (int i = threadIdx.x; i < 5120; i += 256) {
            int p = i & 1, t = i >> 1;
            int nt = t % 20, sl = t / 20;
            int lane = sl & 31, s = sl >> 5;
            int tig = lane & 3, g = lane >> 2;
            int n = nt * 8 + g;
            g_wf[base + i] = *(const float2*)(
                W + (size_t)(c0 + 2 * s + p) * 1280 + n * 8 + 2 * tig);
        }
    } else {
        // agreement W quads (fp32, output-fragment layout — unchanged)
        int chunk = bid - 720;
        int c0 = chunk * CB2;
        size_t base = (size_t)chunk * 5120;
#pragma unroll
        for (int i = threadIdx.x; i < 5120; i += 256) {
            int w = i / 640, rem = i - w * 640, nt = rem >> 5, lane = rem & 31;
            int tig = lane & 3, g = lane >> 2;
            int n = nt * 8 + 2 * tig;
            const float* w0 = W + (size_t)(c0 + g) * 1280 + n * 8 + w;
            const float* w1 = W + (size_t)(c0 + g + 8) * 1280 + n * 8 + w;
            uint4 q;
            q.x = __float_as_uint(w0[0]);
            q.y = __float_as_uint(w0[8]);
            q.z = __float_as_uint(w1[0]);
            q.w = __float_as_uint(w1[8]);
            g_wa[base + i] = q;
        }
    }
}

// ---------------------------------------------------------------------------
// MMA pass: M=128 x N=160 x K=64 in 4 k16 steps, bf16x3.
// A streamed from gmem frags (LDG.128), B frags in smem stride-21 uint4.
// ---------------------------------------------------------------------------
__device__ __forceinline__ void gemm_pass(const uint4* __restrict__ aH,
                                          const uint4* __restrict__ aL,
                                          const uint4* bb4, int tid,
                                          float d[20][4]) {
    int w = tid >> 5, lane = tid & 31;
    const uint4* ah = aH + w * 128 + lane;
    const uint4* al = aL + w * 128 + lane;
#pragma unroll
    for (int s = 0; s < 4; s++) {
        uint4 h = ah[s * 32];
        uint4 l = al[s * 32];
        const uint4* bp = bb4 + (s * 32 + lane) * 21;
#pragma unroll
        for (int nt = 0; nt < 20; nt++) {
            uint4 bq = bp[nt];
            mma16(d[nt], h, bq.x, bq.y);   // hi*hi
            mma16(d[nt], h, bq.z, bq.w);   // hi*lo
            mma16(d[nt], l, bq.x, bq.y);   // lo*hi
        }
    }
}

// ---------------------------------------------------------------------------
// Kernel B (GEMM1): K=64 per block; grid (144,2), block 256, 2 blocks/SM.
// ---------------------------------------------------------------------------
__global__ void __launch_bounds__(256, 2) kernB() {
    extern __shared__ float sm[];
    uint4* bb4 = (uint4*)sm;            // 2688 uint4 = 43008B
    float* cs = sm + 10752;             // 80 floats

    int tid = threadIdx.x;
    int sub = blockIdx.x, half = blockIdx.y;
    int c0 = sub * 8;

    // softmax for 8 capsules
    if (tid < 80) {
        int cl = tid / 10, j = tid - cl * 10;
        const float* br = g_b + (size_t)(c0 + cl) * JJ;
        float bv[JJ], mx = -1e30f;
#pragma unroll
        for (int q = 0; q < JJ; q++) { bv[q] = br[q]; mx = fmaxf(mx, bv[q]); }
        float sum = 0.f;
#pragma unroll
        for (int q = 0; q < JJ; q++) { bv[q] = expf(bv[q] - mx); sum += bv[q]; }
        cs[tid] = bv[j] / sum;
    }
    __syncthreads();

    // B fragments: LDG.128 (two float2) from g_wf, scale, bf16 hi/lo, STS.128
    const float2* wf = g_wf + (size_t)sub * 5120;
#pragma unroll
    for (int i = tid; i < 2560; i += 256) {
        int nt = i % 20, sl = i / 20;
        int lane = sl & 31, s = sl >> 5;
        int g = lane >> 2;
        int j = (nt * 8 + g) >> 4;
        float2 p0 = wf[i * 2];          // cl = 2s
        float2 p1 = wf[i * 2 + 1];      // cl = 2s+1
        float sc0 = cs[(2 * s) * 10 + j];
        float sc1 = cs[(2 * s + 1) * 10 + j];
        uint4 q;
        bfpackhl(sc0 * p0.x, sc0 * p0.y, q.x, q.z);
        bfpackhl(sc1 * p1.x, sc1 * p1.y, q.y, q.w);
        bb4[(s * 32 + lane) * 21 + nt] = q;
    }
    __syncthreads();

    float d[20][4];
#pragma unroll
    for (int nt = 0; nt < 20; nt++)
#pragma unroll
        for (int q = 0; q < 4; q++) d[nt][q] = 0.f;

    const uint4* aH = g_xf1h + ((size_t)sub * 2 + half) * 1024;
    const uint4* aL = g_xf1l + ((size_t)sub * 2 + half) * 1024;
    gemm_pass(aH, aL, bb4, tid, d);

    // direct fragment store (output layout identical to k8 version)
    int w = tid >> 5, lane = tid & 31, g = lane >> 2, tig = lane & 3;
    float* dst = g_spart + ((size_t)sub * BB + half * 128 + w * 16 + g) * JD
               + 2 * tig;
#pragma unroll
    for (int nt = 0; nt < 20; nt++) {
        *(float2*)(dst + nt * 8) = make_float2(d[nt][0], d[nt][1]);
        *(float2*)(dst + 8 * JD + nt * 8) = make_float2(d[nt][2], d[nt][3]);
    }
}

// ---------------------------------------------------------------------------
// Kernel C: reduce 144 split-K partials + squash; writes v bf16-fragments
// into g_vf (and d_out on the final iteration). grid 80, block 512.
// ---------------------------------------------------------------------------
__global__ void __launch_bounds__(512) kernC(float* __restrict__ out) {
    int idx = blockIdx.x * 512 + threadIdx.x;   // b*160 + n
    float s = 1e-5f;                            // ref adds 1e-5 BEFORE magnitudes
    const float* sp = g_spart + idx;
#pragma unroll 8
    for (int ch = 0; ch < NSUB; ch++)
        s += sp[(size_t)ch * (BB * JD)];

    float mag = s * s;
#pragma unroll
    for (int off = 8; off; off >>= 1)
        mag += __shfl_xor_sync(0xffffffffu, mag, off, 16);

    float v = s * (mag / ((1.f + mag) * sqrtf(mag)));

    // scatter v (bf16 hi/lo) into k16 fragment slots
    int b = idx / JD, n = idx - b * JD;
    int slice = b >> 6, kc = b & 63;
    int st = kc >> 4, klocal = kc & 15;
    int p = klocal >> 3, kl7 = klocal & 7;
    int tig = kl7 >> 1, e = kl7 & 1;
    int lane = (n & 7) * 4 + tig, nt = n >> 3;
    uint16_t h, l;
    bfhilo1(v, h, l);
    size_t vi = (size_t)slice * 2560 + (st * 32 + lane) * 20 + nt;
    uint16_t* vb = (uint16_t*)g_vf + vi * 8;
    vb[p * 2 + e] = h;            // hi words .x/.y
    vb[(2 + p) * 2 + e] = l;      // lo words .z/.w

    if (out) out[idx] = v;                      // (B,J,D,1) same linearization
}

// ---------------------------------------------------------------------------
// Kernel D (GEMM2): grid (72,4), block 256; fragment-space agreement
// (no G staging, no scattered W reads) — unchanged epilogue math.
// ---------------------------------------------------------------------------
__global__ void __launch_bounds__(256, 2) kernD() {
    extern __shared__ float sm[];
    uint4* bb4 = (uint4*)sm;            // 2688 uint4
    float* sAg = sm + 10752;            // 160 floats: agreement[cl][j]

    int tid = threadIdx.x;
    int chunk = blockIdx.x, slice = blockIdx.y;
    int c0 = chunk * CB2;

    if (tid < 160) sAg[tid] = 0.f;

    // B fragments: pure coalesced copy from g_vf (pad stride 20 -> 21)
    const uint4* vf = g_vf + (size_t)slice * 2560;
#pragma unroll
    for (int i = tid; i < 2560; i += 256) {
        int nt = i % 20, sl = i / 20;
        int lane = sl & 31, st = sl >> 5;
        bb4[(st * 32 + lane) * 21 + nt] = vf[i];
    }
    __syncthreads();

    float d[20][4];
#pragma unroll
    for (int nt = 0; nt < 20; nt++)
#pragma unroll
        for (int q = 0; q < 4; q++) d[nt][q] = 0.f;

    const uint4* aH = g_xf2h + ((size_t)chunk * 4 + slice) * 1024;
    const uint4* aL = g_xf2l + ((size_t)chunk * 4 + slice) * 1024;
    gemm_pass(aH, aL, bb4, tid, d);

    // fragment-space agreement (output layout unchanged): thread (w=kin, lane)
    // holds d[nt] = {G[kin16+g][n], [n+1], G[kin16+g+8][n], [n+1]}, j = nt>>1
    int w = tid >> 5, lane = tid & 31, g = lane >> 2, tig = lane & 3;
    float ag0[10], ag1[10];
#pragma unroll
    for (int j = 0; j < 10; j++) { ag0[j] = 0.f; ag1[j] = 0.f; }

    const uint4* wap = g_wa + (size_t)chunk * 5120 + w * 640 + lane;
#pragma unroll
    for (int nt = 0; nt < 20; nt++) {
        uint4 q = wap[nt * 32];
        float wx = __uint_as_float(q.x), wy = __uint_as_float(q.y);
        float wz = __uint_as_float(q.z), ww = __uint_as_float(q.w);
        int j = nt >> 1;
        ag0[j] = fmaf(wx, d[nt][0], fmaf(wy, d[nt][1], ag0[j]));
        ag1[j] = fmaf(wz, d[nt][2], fmaf(ww, d[nt][3], ag1[j]));
    }
#pragma unroll
    for (int j = 0; j < 10; j++) {
        ag0[j] += __shfl_xor_sync(0xffffffffu, ag0[j], 1, 4);
        ag0[j] += __shfl_xor_sync(0xffffffffu, ag0[j], 2, 4);
        ag1[j] += __shfl_xor_sync(0xffffffffu, ag1[j], 1, 4);
        ag1[j] += __shfl_xor_sync(0xffffffffu, ag1[j], 2, 4);
    }
    if (tig == 0) {
#pragma unroll
        for (int j = 0; j < 10; j++) {
            atomicAdd(&sAg[g * 10 + j], ag0[j]);
            atomicAdd(&sAg[(g + 8) * 10 + j], ag1[j]);
        }
    }
    __syncthreads();

    if (tid < 160)
        atomicAdd(&g_b[c0 * JJ + tid], sAg[tid]);   // [cl][j] contiguous
}

// ---------------------------------------------------------------------------
// Host launcher (graph-capturable)
// ---------------------------------------------------------------------------
extern "C" void kernel_launch(void* const* d_in, const int* in_sizes, int n_in,
                              void* d_out, int out_size) {
    const float* x = (const float*)d_in[0];
    const float* W = (const float*)d_in[1];
    if (in_sizes[0] != BB * XKC) {   // defensive mapping by element count
        x = (const float*)d_in[1];
        W = (const float*)d_in[0];
    }

    cudaFuncSetAttribute(kernB, cudaFuncAttributeMaxDynamicSharedMemorySize, SMEMB1);
    cudaFuncSetAttribute(kernD, cudaFuncAttributeMaxDynamicSharedMemorySize, SMEMB2);

    void* pb = nullptr;
    cudaGetSymbolAddress(&pb, g_b);
    cudaMemsetAsync(pb, 0, CC * JJ * sizeof(float));   // b_ij = 0 each call

    prepAll<<<792, 256>>>(x, W);                       // all frags, one launch

    dim3 gB(NSUB, 2);    // (144, 2)
    dim3 gD(NCH2, 4);    // (72, 4)
    for (int it = 0; it < 4; it++) {
        kernB<<<gB, 256, SMEMB1>>>();                           // bf16x3 GEMM1
        kernC<<<(BB * JD) / 512, 512>>>(it == 3 ? (float*)d_out : nullptr);
        if (it < 3)                                             // iter-4 agreement dead
            kernD<<<gD, 256, SMEMB2>>>();                       // bf16x3 GEMM2
    }
}

// round 16
// speedup vs baseline: 1.6812x; 1.1480x over previous
#include <cuda_runtime.h>
#include <cuda_bf16.h>
#include <math.h>
#include <stdint.h>

// Problem constants
#define BB   256
#define KIN  8
#define CC   1152
#define JJ   10
#define DD   16
#define JD   160
#define XKC  9216          // KIN*CC

// fragment granularity: 8-capsule sub-chunks (144); kernB chunks: 16 caps (72)
#define NSUB 144
#define NCHK 72
// GEMM2: 16-capsule chunks (M=128 rows), K=64 batch slice
#define CB2  16
#define NCH2 72

#define SMEMB1 45696       // 2816 uint4 B frags (45056) + cs[160]
#define SMEMB2 43648       // 2688 uint4 B frags + sAg[160]

// ---------------------------------------------------------------------------
// Device globals (runtime allocation forbidden)
// ---------------------------------------------------------------------------
__device__ alignas(16) float g_spart[NCHK * BB * JD];   // split-K partials (11.8MB)
__device__ alignas(16) uint4 g_xf1h[NSUB * 2 * 1024];   // GEMM1 A-frag hi bf16
__device__ alignas(16) uint4 g_xf1l[NSUB * 2 * 1024];   // GEMM1 A-frag lo
__device__ alignas(16) uint4 g_xf2h[NCH2 * 4 * 1024];   // GEMM2 A-frag hi
__device__ alignas(16) uint4 g_xf2l[NCH2 * 4 * 1024];   // GEMM2 A-frag lo
__device__ alignas(16) float2 g_wf[NSUB * 5120];        // W frag pairs (5.9MB)
__device__ alignas(16) uint4 g_wa[NCH2 * 5120];         // agreement W quads (5.9MB)
__device__ alignas(16) uint4 g_vf[4 * 2560];            // v bf16 frags per b-slice
__device__ alignas(16) float g_b[CC * JJ];              // routing logits

// bf16 hi/lo split + pack (element with LOWER k index in LOW 16 bits)
__device__ __forceinline__ void bfpackhl(float v0, float v1,
                                         uint32_t& hp, uint32_t& lp) {
    __nv_bfloat16 h0 = __float2bfloat16(v0);
    __nv_bfloat16 h1 = __float2bfloat16(v1);
    __nv_bfloat16 l0 = __float2bfloat16(v0 - __bfloat162float(h0));
    __nv_bfloat16 l1 = __float2bfloat16(v1 - __bfloat162float(h1));
    hp = (uint32_t)__bfloat16_as_ushort(h0) | ((uint32_t)__bfloat16_as_ushort(h1) << 16);
    lp = (uint32_t)__bfloat16_as_ushort(l0) | ((uint32_t)__bfloat16_as_ushort(l1) << 16);
}
__device__ __forceinline__ void bfhilo1(float v, uint16_t& h, uint16_t& l) {
    __nv_bfloat16 bh = __float2bfloat16(v);
    __nv_bfloat16 bl = __float2bfloat16(v - __bfloat162float(bh));
    h = __bfloat16_as_ushort(bh);
    l = __bfloat16_as_ushort(bl);
}
__device__ __forceinline__ void mma16(float* d, const uint4& a,
                                      uint32_t b0, uint32_t b1) {
    asm volatile(
        "mma.sync.aligned.m16n8k16.row.col.f32.bf16.bf16.f32 "
        "{%0,%1,%2,%3}, {%4,%5,%6,%7}, {%8,%9}, {%0,%1,%2,%3};"
        : "+f"(d[0]), "+f"(d[1]), "+f"(d[2]), "+f"(d[3])
        : "r"(a.x), "r"(a.y), "r"(a.z), "r"(a.w), "r"(b0), "r"(b1));
}

// ---------------------------------------------------------------------------
// prepAll: one-time fragment preparation, single 792-block launch.
// (identical layouts to the R15 passing kernel)
// ---------------------------------------------------------------------------
__global__ void __launch_bounds__(256) prepAll(const float* __restrict__ x,
                                               const float* __restrict__ W) {
    int bid = blockIdx.x;
    if (bid < 288) {
        int sub = bid >> 1, half = bid & 1;
        int c0 = sub * 8, b0 = half * 128;
        size_t base = (size_t)bid * 1024;
#pragma unroll
        for (int i = threadIdx.x; i < 1024; i += 256) {
            int w = i >> 7, s = (i >> 5) & 3, lane = i & 31;
            int tig = lane & 3, g = lane >> 2;
            int m0 = w * 16 + g;
            const float* xb = x + (size_t)(b0 + m0) * XKC + (2 * tig) * CC + c0;
            uint4 h, l;
            bfpackhl(xb[2 * s], xb[CC + 2 * s], h.x, l.x);               // rows m0, cl=2s
            bfpackhl(xb[8 * XKC + 2 * s], xb[8 * XKC + CC + 2 * s], h.y, l.y);
            bfpackhl(xb[2 * s + 1], xb[CC + 2 * s + 1], h.z, l.z);       // cl=2s+1
            bfpackhl(xb[8 * XKC + 2 * s + 1], xb[8 * XKC + CC + 2 * s + 1], h.w, l.w);
            g_xf1h[base + i] = h;
            g_xf1l[base + i] = l;
        }
    } else if (bid < 576) {
        int idx = bid - 288;
        int chunk = idx >> 2, slice = idx & 3;
        int c0 = chunk * CB2, b0 = slice * 64;
        size_t base = (size_t)idx * 1024;
#pragma unroll
        for (int i = threadIdx.x; i < 1024; i += 256) {
            int w = i >> 7, s = (i >> 5) & 3, lane = i & 31;
            int tig = lane & 3, g = lane >> 2;
            const float* xb = x + (size_t)(b0 + s * 16 + 2 * tig) * XKC + w * CC + c0;
            uint4 h, l;
            bfpackhl(xb[g], xb[XKC + g], h.x, l.x);                       // r=w16+g
            bfpackhl(xb[g + 8], xb[XKC + g + 8], h.y, l.y);               // r=w16+g+8
            bfpackhl(xb[8 * XKC + g], xb[9 * XKC + g], h.z, l.z);         // b pair1
            bfpackhl(xb[8 * XKC + g + 8], xb[9 * XKC + g + 8], h.w, l.w);
            g_xf2h[base + i] = h;
            g_xf2l[base + i] = l;
        }
    } else if (bid < 720) {
        // W frag pairs: i = ((s*32+lane)*20+nt)*2+p ; value = W[c0+2s+p, n, 2tig..+1]
        int sub = bid - 576;
        int c0 = sub * 8;
        size_t base = (size_t)sub * 5120;
#pragma unroll
        for (int i = threadIdx.x; i < 5120; i += 256) {
            int p = i & 1, t = i >> 1;
            int nt = t % 20, sl = t / 20;
            int lane = sl & 31, s = sl >> 5;
            int tig = lane & 3, g = lane >> 2;
            int n = nt * 8 + g;
            g_wf[base + i] = *(const float2*)(
                W + (size_t)(c0 + 2 * s + p) * 1280 + n * 8 + 2 * tig);
        }
    } else {
        // agreement W quads (fp32, output-fragment layout)
        int chunk = bid - 720;
        int c0 = chunk * CB2;
        size_t base = (size_t)chunk * 5120;
#pragma unroll
        for (int i = threadIdx.x; i < 5120; i += 256) {
            int w = i / 640, rem = i - w * 640, nt = rem >> 5, lane = rem & 31;
            int tig = lane & 3, g = lane >> 2;
            int n = nt * 8 + 2 * tig;
            const float* w0 = W + (size_t)(c0 + g) * 1280 + n * 8 + w;
            const float* w1 = W + (size_t)(c0 + g + 8) * 1280 + n * 8 + w;
            uint4 q;
            q.x = __float_as_uint(w0[0]);
            q.y = __float_as_uint(w0[8]);
            q.z = __float_as_uint(w1[0]);
            q.w = __float_as_uint(w1[8]);
            g_wa[base + i] = q;
        }
    }
}

// ---------------------------------------------------------------------------
// Kernel B (GEMM1): M=128 x N=80 x K=128 per block; grid (72, 2 bhalf, 2 nhalf)
// = 288 blocks, 2 blocks/SM, 1 wave. All 8 k16-steps staged in one smem pass.
// ---------------------------------------------------------------------------
__global__ void __launch_bounds__(256, 2) kernB() {
    extern __shared__ float sm[];
    uint4* bb4 = (uint4*)sm;            // 2816 uint4 = 45056B
    float* cs = sm + 11264;             // 160 floats

    int tid = threadIdx.x;
    int cp = blockIdx.x, half = blockIdx.y, nh = blockIdx.z;
    int c0 = cp * 16;

    // softmax for 16 capsules
    if (tid < 160) {
        int cl = tid / 10, j = tid - cl * 10;
        const float* br = g_b + (size_t)(c0 + cl) * JJ;
        float bv[JJ], mx = -1e30f;
#pragma unroll
        for (int q = 0; q < JJ; q++) { bv[q] = br[q]; mx = fmaxf(mx, bv[q]); }
        float sum = 0.f;
#pragma unroll
        for (int q = 0; q < JJ; q++) { bv[q] = expf(bv[q] - mx); sum += bv[q]; }
        cs[tid] = bv[j] / sum;
    }
    __syncthreads();

    // B fragments for all 8 k16-steps (step s: sub = cp*2+(s>>2), slocal = s&3)
#pragma unroll
    for (int i = tid; i < 2560; i += 256) {
        int ntl = i % 10, sl = i / 10;
        int lane = sl & 31, s = sl >> 5;          // s 0..7
        int p = s >> 2, slocal = s & 3;
        int sub = cp * 2 + p;
        int g = lane >> 2;
        int j = ((nh * 10 + ntl) * 8 + g) >> 4;
        const float2* wfb = g_wf + (size_t)sub * 5120
                          + ((slocal * 32 + lane) * 20 + nh * 10 + ntl) * 2;
        float2 p0 = wfb[0];                       // capsule parity 0 (cl = 2*slocal)
        float2 p1 = wfb[1];                       // capsule parity 1
        float sc0 = cs[(p * 8 + 2 * slocal) * 10 + j];
        float sc1 = cs[(p * 8 + 2 * slocal + 1) * 10 + j];
        uint4 q;
        bfpackhl(sc0 * p0.x, sc0 * p0.y, q.x, q.z);
        bfpackhl(sc1 * p1.x, sc1 * p1.y, q.y, q.w);
        bb4[(s * 32 + lane) * 11 + ntl] = q;
    }
    __syncthreads();

    float d[10][4];
#pragma unroll
    for (int nt = 0; nt < 10; nt++)
#pragma unroll
        for (int q = 0; q < 4; q++) d[nt][q] = 0.f;

    int w = tid >> 5, lane = tid & 31;
    // A-frag bases: sub = cp*2 (p=0) at +0, p=1 at +2048 uint4
    const uint4* aH0 = g_xf1h + ((size_t)cp * 4 + half) * 1024 + w * 128 + lane;
    const uint4* aL0 = g_xf1l + ((size_t)cp * 4 + half) * 1024 + w * 128 + lane;
#pragma unroll
    for (int s = 0; s < 8; s++) {
        int p = s >> 2, slocal = s & 3;
        uint4 h = aH0[p * 2048 + slocal * 32];
        uint4 l = aL0[p * 2048 + slocal * 32];
        const uint4* bp = bb4 + (s * 32 + lane) * 11;
#pragma unroll
        for (int nt = 0; nt < 10; nt++) {
            uint4 bq = bp[nt];
            mma16(d[nt], h, bq.x, bq.y);   // hi*hi
            mma16(d[nt], h, bq.z, bq.w);   // hi*lo
            mma16(d[nt], l, bq.x, bq.y);   // lo*hi
        }
    }

    // direct fragment store
    int g = lane >> 2, tig = lane & 3;
    float* dst = g_spart + ((size_t)cp * BB + half * 128 + w * 16 + g) * JD
               + nh * 80 + 2 * tig;
#pragma unroll
    for (int nt = 0; nt < 10; nt++) {
        *(float2*)(dst + nt * 8) = make_float2(d[nt][0], d[nt][1]);
        *(float2*)(dst + 8 * JD + nt * 8) = make_float2(d[nt][2], d[nt][3]);
    }
}

// ---------------------------------------------------------------------------
// Kernel C: reduce 72 split-K partials + squash; writes v bf16-fragments
// into g_vf (and d_out on the final iteration). grid 80, block 512.
// ---------------------------------------------------------------------------
__global__ void __launch_bounds__(512) kernC(float* __restrict__ out) {
    int idx = blockIdx.x * 512 + threadIdx.x;   // b*160 + n
    float s = 1e-5f;                            // ref adds 1e-5 BEFORE magnitudes
    const float* sp = g_spart + idx;
#pragma unroll 8
    for (int ch = 0; ch < NCHK; ch++)
        s += sp[(size_t)ch * (BB * JD)];

    float mag = s * s;
#pragma unroll
    for (int off = 8; off; off >>= 1)
        mag += __shfl_xor_sync(0xffffffffu, mag, off, 16);

    float v = s * (mag / ((1.f + mag) * sqrtf(mag)));

    // scatter v (bf16 hi/lo) into k16 fragment slots
    int b = idx / JD, n = idx - b * JD;
    int slice = b >> 6, kc = b & 63;
    int st = kc >> 4, klocal = kc & 15;
    int p = klocal >> 3, kl7 = klocal & 7;
    int tig = kl7 >> 1, e = kl7 & 1;
    int lane = (n & 7) * 4 + tig, nt = n >> 3;
    uint16_t h, l;
    bfhilo1(v, h, l);
    size_t vi = (size_t)slice * 2560 + (st * 32 + lane) * 20 + nt;
    uint16_t* vb = (uint16_t*)g_vf + vi * 8;
    vb[p * 2 + e] = h;            // hi words .x/.y
    vb[(2 + p) * 2 + e] = l;      // lo words .z/.w

    if (out) out[idx] = v;                      // (B,J,D,1) same linearization
}

// ---------------------------------------------------------------------------
// Kernel D (GEMM2): grid (72,4), block 256; fragment-space agreement
// (no G staging, no scattered W reads) — unchanged from R15.
// ---------------------------------------------------------------------------
__global__ void __launch_bounds__(256, 2) kernD() {
    extern __shared__ float sm[];
    uint4* bb4 = (uint4*)sm;            // 2688 uint4
    float* sAg = sm + 10752;            // 160 floats: agreement[cl][j]

    int tid = threadIdx.x;
    int chunk = blockIdx.x, slice = blockIdx.y;
    int c0 = chunk * CB2;

    if (tid < 160) sAg[tid] = 0.f;

    // B fragments: pure coalesced copy from g_vf (pad stride 20 -> 21)
    const uint4* vf = g_vf + (size_t)slice * 2560;
#pragma unroll
    for (int i = tid; i < 2560; i += 256) {
        int nt = i % 20, sl = i / 20;
        int lane = sl & 31, st = sl >> 5;
        bb4[(st * 32 + lane) * 21 + nt] = vf[i];
    }
    __syncthreads();

    float d[20][4];
#pragma unroll
    for (int nt = 0; nt < 20; nt++)
#pragma unroll
        for (int q = 0; q < 4; q++) d[nt][q] = 0.f;

    int w = tid >> 5, lane = tid & 31;
    const uint4* ah = g_xf2h + ((size_t)chunk * 4 + slice) * 1024 + w * 128 + lane;
    const uint4* al = g_xf2l + ((size_t)chunk * 4 + slice) * 1024 + w * 128 + lane;
#pragma unroll
    for (int s = 0; s < 4; s++) {
        uint4 h = ah[s * 32];
        uint4 l = al[s * 32];
        const uint4* bp = bb4 + (s * 32 + lane) * 21;
#pragma unroll
        for (int nt = 0; nt < 20; nt++) {
            uint4 bq = bp[nt];
            mma16(d[nt], h, bq.x, bq.y);   // hi*hi
            mma16(d[nt], h, bq.z, bq.w);   // hi*lo
            mma16(d[nt], l, bq.x, bq.y);   // lo*hi
        }
    }

    // fragment-space agreement: thread (w=kin, lane) holds
    // d[nt] = {G[kin16+g][n], [n+1], G[kin16+g+8][n], [n+1]}, j = nt>>1
    int g = lane >> 2, tig = lane & 3;
    float ag0[10], ag1[10];
#pragma unroll
    for (int j = 0; j < 10; j++) { ag0[j] = 0.f; ag1[j] = 0.f; }

    const uint4* wap = g_wa + (size_t)chunk * 5120 + w * 640 + lane;
#pragma unroll
    for (int nt = 0; nt < 20; nt++) {
        uint4 q = wap[nt * 32];
        float wx = __uint_as_float(q.x), wy = __uint_as_float(q.y);
        float wz = __uint_as_float(q.z), ww = __uint_as_float(q.w);
        int j = nt >> 1;
        ag0[j] = fmaf(wx, d[nt][0], fmaf(wy, d[nt][1], ag0[j]));
        ag1[j] = fmaf(wz, d[nt][2], fmaf(ww, d[nt][3], ag1[j]));
    }
#pragma unroll
    for (int j = 0; j < 10; j++) {
        ag0[j] += __shfl_xor_sync(0xffffffffu, ag0[j], 1, 4);
        ag0[j] += __shfl_xor_sync(0xffffffffu, ag0[j], 2, 4);
        ag1[j] += __shfl_xor_sync(0xffffffffu, ag1[j], 1, 4);
        ag1[j] += __shfl_xor_sync(0xffffffffu, ag1[j], 2, 4);
    }
    if (tig == 0) {
#pragma unroll
        for (int j = 0; j < 10; j++) {
            atomicAdd(&sAg[g * 10 + j], ag0[j]);
            atomicAdd(&sAg[(g + 8) * 10 + j], ag1[j]);
        }
    }
    __syncthreads();

    if (tid < 160)
        atomicAdd(&g_b[c0 * JJ + tid], sAg[tid]);   // [cl][j] contiguous
}

// ---------------------------------------------------------------------------
// Host launcher (graph-capturable)
// ---------------------------------------------------------------------------
extern "C" void kernel_launch(void* const* d_in, const int* in_sizes, int n_in,
                              void* d_out, int out_size) {
    const float* x = (const float*)d_in[0];
    const float* W = (const float*)d_in[1];
    if (in_sizes[0] != BB * XKC) {   // defensive mapping by element count
        x = (const float*)d_in[1];
        W = (const float*)d_in[0];
    }

    cudaFuncSetAttribute(kernB, cudaFuncAttributeMaxDynamicSharedMemorySize, SMEMB1);
    cudaFuncSetAttribute(kernD, cudaFuncAttributeMaxDynamicSharedMemorySize, SMEMB2);

    void* pb = nullptr;
    cudaGetSymbolAddress(&pb, g_b);
    cudaMemsetAsync(pb, 0, CC * JJ * sizeof(float));   // b_ij = 0 each call

    prepAll<<<792, 256>>>(x, W);                       // all frags, one launch

    dim3 gB(NCHK, 2, 2);    // (72, 2 bhalf, 2 nhalf) = 288 blocks
    dim3 gD(NCH2, 4);       // (72, 4)
    for (int it = 0; it < 4; it++) {
        kernB<<<gB, 256, SMEMB1>>>();                           // bf16x3 GEMM1
        kernC<<<(BB * JD) / 512, 512>>>(it == 3 ? (float*)d_out : nullptr);
        if (it < 3)                                             // iter-4 agreement dead
            kernD<<<gD, 256, SMEMB2>>>();                       // bf16x3 GEMM2
    }
}

// round 17
// speedup vs baseline: 1.7025x; 1.0127x over previous
#include <cuda_runtime.h>
#include <cuda_bf16.h>
#include <math.h>
#include <stdint.h>

// Problem constants
#define BB   256
#define KIN  8
#define CC   1152
#define JJ   10
#define DD   16
#define JD   160
#define XKC  9216          // KIN*CC

// fragment granularity: 8-capsule sub-chunks (144); GEMM chunks: 16 caps (72)
#define NSUB 144
#define NCHK 72
#define CB2  16
#define NCH2 72

#define SMEMB1 45696       // 2816 uint4 B frags (45056) + cs[160]
#define SMEMB2 45376       // 2816 uint4 B frags (45056) + sAg[80]

// ---------------------------------------------------------------------------
// Device globals (runtime allocation forbidden)
// ---------------------------------------------------------------------------
__device__ alignas(16) float g_spart[NCHK * BB * JD];   // split-K partials (11.8MB)
__device__ alignas(16) uint4 g_xf1h[NSUB * 2 * 1024];   // GEMM1 A-frag hi bf16
__device__ alignas(16) uint4 g_xf1l[NSUB * 2 * 1024];   // GEMM1 A-frag lo
__device__ alignas(16) uint4 g_xf2h[NCH2 * 4 * 1024];   // GEMM2 A-frag hi
__device__ alignas(16) uint4 g_xf2l[NCH2 * 4 * 1024];   // GEMM2 A-frag lo
__device__ alignas(16) float2 g_wf[NSUB * 5120];        // W frag pairs (5.9MB)
__device__ alignas(16) uint4 g_wa[NCH2 * 5120];         // agreement W quads (5.9MB)
__device__ alignas(16) uint4 g_vf[4 * 2560];            // v bf16 frags per b-slice
__device__ alignas(16) float g_b[CC * JJ];              // routing logits

// bf16 hi/lo split + pack (element with LOWER k index in LOW 16 bits)
__device__ __forceinline__ void bfpackhl(float v0, float v1,
                                         uint32_t& hp, uint32_t& lp) {
    __nv_bfloat16 h0 = __float2bfloat16(v0);
    __nv_bfloat16 h1 = __float2bfloat16(v1);
    __nv_bfloat16 l0 = __float2bfloat16(v0 - __bfloat162float(h0));
    __nv_bfloat16 l1 = __float2bfloat16(v1 - __bfloat162float(h1));
    hp = (uint32_t)__bfloat16_as_ushort(h0) | ((uint32_t)__bfloat16_as_ushort(h1) << 16);
    lp = (uint32_t)__bfloat16_as_ushort(l0) | ((uint32_t)__bfloat16_as_ushort(l1) << 16);
}
__device__ __forceinline__ void bfhilo1(float v, uint16_t& h, uint16_t& l) {
    __nv_bfloat16 bh = __float2bfloat16(v);
    __nv_bfloat16 bl = __float2bfloat16(v - __bfloat162float(bh));
    h = __bfloat16_as_ushort(bh);
    l = __bfloat16_as_ushort(bl);
}
__device__ __forceinline__ void mma16(float* d, const uint4& a,
                                      uint32_t b0, uint32_t b1) {
    asm volatile(
        "mma.sync.aligned.m16n8k16.row.col.f32.bf16.bf16.f32 "
        "{%0,%1,%2,%3}, {%4,%5,%6,%7}, {%8,%9}, {%0,%1,%2,%3};"
        : "+f"(d[0]), "+f"(d[1]), "+f"(d[2]), "+f"(d[3])
        : "r"(a.x), "r"(a.y), "r"(a.z), "r"(a.w), "r"(b0), "r"(b1));
}

// ---------------------------------------------------------------------------
// prepAll: one-time fragment preparation, single 792-block launch.
// (identical layouts to the R15/R16 passing kernels)
// ---------------------------------------------------------------------------
__global__ void __launch_bounds__(256) prepAll(const float* __restrict__ x,
                                               const float* __restrict__ W) {
    int bid = blockIdx.x;
    if (bid < 288) {
        int sub = bid >> 1, half = bid & 1;
        int c0 = sub * 8, b0 = half * 128;
        size_t base = (size_t)bid * 1024;
#pragma unroll
        for (int i = threadIdx.x; i < 1024; i += 256) {
            int w = i >> 7, s = (i >> 5) & 3, lane = i & 31;
            int tig = lane & 3, g = lane >> 2;
            int m0 = w * 16 + g;
            const float* xb = x + (size_t)(b0 + m0) * XKC + (2 * tig) * CC + c0;
            uint4 h, l;
            bfpackhl(xb[2 * s], xb[CC + 2 * s], h.x, l.x);               // rows m0, cl=2s
            bfpackhl(xb[8 * XKC + 2 * s], xb[8 * XKC + CC + 2 * s], h.y, l.y);
            bfpackhl(xb[2 * s + 1], xb[CC + 2 * s + 1], h.z, l.z);       // cl=2s+1
            bfpackhl(xb[8 * XKC + 2 * s + 1], xb[8 * XKC + CC + 2 * s + 1], h.w, l.w);
            g_xf1h[base + i] = h;
            g_xf1l[base + i] = l;
        }
    } else if (bid < 576) {
        int idx = bid - 288;
        int chunk = idx >> 2, slice = idx & 3;
        int c0 = chunk * CB2, b0 = slice * 64;
        size_t base = (size_t)idx * 1024;
#pragma unroll
        for (int i = threadIdx.x; i < 1024; i += 256) {
            int w = i >> 7, s = (i >> 5) & 3, lane = i & 31;
            int tig = lane & 3, g = lane >> 2;
            const float* xb = x + (size_t)(b0 + s * 16 + 2 * tig) * XKC + w * CC + c0;
            uint4 h, l;
            bfpackhl(xb[g], xb[XKC + g], h.x, l.x);                       // r=w16+g
            bfpackhl(xb[g + 8], xb[XKC + g + 8], h.y, l.y);               // r=w16+g+8
            bfpackhl(xb[8 * XKC + g], xb[9 * XKC + g], h.z, l.z);         // b pair1
            bfpackhl(xb[8 * XKC + g + 8], xb[9 * XKC + g + 8], h.w, l.w);
            g_xf2h[base + i] = h;
            g_xf2l[base + i] = l;
        }
    } else if (bid < 720) {
        // W frag pairs: i = ((s*32+lane)*20+nt)*2+p ; value = W[c0+2s+p, n, 2tig..+1]
        int sub = bid - 576;
        int c0 = sub * 8;
        size_t base = (size_t)sub * 5120;
#pragma unroll
        for (int i = threadIdx.x; i < 5120; i += 256) {
            int p = i & 1, t = i >> 1;
            int nt = t % 20, sl = t / 20;
            int lane = sl & 31, s = sl >> 5;
            int tig = lane & 3, g = lane >> 2;
            int n = nt * 8 + g;
            g_wf[base + i] = *(const float2*)(
                W + (size_t)(c0 + 2 * s + p) * 1280 + n * 8 + 2 * tig);
        }
    } else {
        // agreement W quads (fp32, output-fragment layout)
        int chunk = bid - 720;
        int c0 = chunk * CB2;
        size_t base = (size_t)chunk * 5120;
#pragma unroll
        for (int i = threadIdx.x; i < 5120; i += 256) {
            int w = i / 640, rem = i - w * 640, nt = rem >> 5, lane = rem & 31;
            int tig = lane & 3, g = lane >> 2;
            int n = nt * 8 + 2 * tig;
            const float* w0 = W + (size_t)(c0 + g) * 1280 + n * 8 + w;
            const float* w1 = W + (size_t)(c0 + g + 8) * 1280 + n * 8 + w;
            uint4 q;
            q.x = __float_as_uint(w0[0]);
            q.y = __float_as_uint(w0[8]);
            q.z = __float_as_uint(w1[0]);
            q.w = __float_as_uint(w1[8]);
            g_wa[base + i] = q;
        }
    }
}

// ---------------------------------------------------------------------------
// Kernel B (GEMM1): M=128 x N=80 x K=128 per block; grid (72, 2 bhalf, 2 nhalf)
// = 288 blocks, 2 blocks/SM, 1 wave. (unchanged from R16 passing kernel)
// ---------------------------------------------------------------------------
__global__ void __launch_bounds__(256, 2) kernB() {
    extern __shared__ float sm[];
    uint4* bb4 = (uint4*)sm;            // 2816 uint4 = 45056B
    float* cs = sm + 11264;             // 160 floats

    int tid = threadIdx.x;
    int cp = blockIdx.x, half = blockIdx.y, nh = blockIdx.z;
    int c0 = cp * 16;

    // softmax for 16 capsules
    if (tid < 160) {
        int cl = tid / 10, j = tid - cl * 10;
        const float* br = g_b + (size_t)(c0 + cl) * JJ;
        float bv[JJ], mx = -1e30f;
#pragma unroll
        for (int q = 0; q < JJ; q++) { bv[q] = br[q]; mx = fmaxf(mx, bv[q]); }
        float sum = 0.f;
#pragma unroll
        for (int q = 0; q < JJ; q++) { bv[q] = expf(bv[q] - mx); sum += bv[q]; }
        cs[tid] = bv[j] / sum;
    }
    __syncthreads();

    // B fragments for all 8 k16-steps (step s: sub = cp*2+(s>>2), slocal = s&3)
#pragma unroll
    for (int i = tid; i < 2560; i += 256) {
        int ntl = i % 10, sl = i / 10;
        int lane = sl & 31, s = sl >> 5;          // s 0..7
        int p = s >> 2, slocal = s & 3;
        int sub = cp * 2 + p;
        int g = lane >> 2;
        int j = ((nh * 10 + ntl) * 8 + g) >> 4;
        const float2* wfb = g_wf + (size_t)sub * 5120
                          + ((slocal * 32 + lane) * 20 + nh * 10 + ntl) * 2;
        float2 p0 = wfb[0];                       // capsule parity 0 (cl = 2*slocal)
        float2 p1 = wfb[1];                       // capsule parity 1
        float sc0 = cs[(p * 8 + 2 * slocal) * 10 + j];
        float sc1 = cs[(p * 8 + 2 * slocal + 1) * 10 + j];
        uint4 q;
        bfpackhl(sc0 * p0.x, sc0 * p0.y, q.x, q.z);
        bfpackhl(sc1 * p1.x, sc1 * p1.y, q.y, q.w);
        bb4[(s * 32 + lane) * 11 + ntl] = q;
    }
    __syncthreads();

    float d[10][4];
#pragma unroll
    for (int nt = 0; nt < 10; nt++)
#pragma unroll
        for (int q = 0; q < 4; q++) d[nt][q] = 0.f;

    int w = tid >> 5, lane = tid & 31;
    const uint4* aH0 = g_xf1h + ((size_t)cp * 4 + half) * 1024 + w * 128 + lane;
    const uint4* aL0 = g_xf1l + ((size_t)cp * 4 + half) * 1024 + w * 128 + lane;
#pragma unroll
    for (int s = 0; s < 8; s++) {
        int p = s >> 2, slocal = s & 3;
        uint4 h = aH0[p * 2048 + slocal * 32];
        uint4 l = aL0[p * 2048 + slocal * 32];
        const uint4* bp = bb4 + (s * 32 + lane) * 11;
#pragma unroll
        for (int nt = 0; nt < 10; nt++) {
            uint4 bq = bp[nt];
            mma16(d[nt], h, bq.x, bq.y);   // hi*hi
            mma16(d[nt], h, bq.z, bq.w);   // hi*lo
            mma16(d[nt], l, bq.x, bq.y);   // lo*hi
        }
    }

    // direct fragment store
    int g = lane >> 2, tig = lane & 3;
    float* dst = g_spart + ((size_t)cp * BB + half * 128 + w * 16 + g) * JD
               + nh * 80 + 2 * tig;
#pragma unroll
    for (int nt = 0; nt < 10; nt++) {
        *(float2*)(dst + nt * 8) = make_float2(d[nt][0], d[nt][1]);
        *(float2*)(dst + 8 * JD + nt * 8) = make_float2(d[nt][2], d[nt][3]);
    }
}

// ---------------------------------------------------------------------------
// Kernel C: reduce 72 split-K partials + squash; writes v bf16-fragments
// into g_vf (and d_out on the final iteration). grid 80, block 512.
// ---------------------------------------------------------------------------
__global__ void __launch_bounds__(512) kernC(float* __restrict__ out) {
    int idx = blockIdx.x * 512 + threadIdx.x;   // b*160 + n
    float s = 1e-5f;                            // ref adds 1e-5 BEFORE magnitudes
    const float* sp = g_spart + idx;
#pragma unroll 8
    for (int ch = 0; ch < NCHK; ch++)
        s += sp[(size_t)ch * (BB * JD)];

    float mag = s * s;
#pragma unroll
    for (int off = 8; off; off >>= 1)
        mag += __shfl_xor_sync(0xffffffffu, mag, off, 16);

    float v = s * (mag / ((1.f + mag) * sqrtf(mag)));

    // scatter v (bf16 hi/lo) into k16 fragment slots
    int b = idx / JD, n = idx - b * JD;
    int slice = b >> 6, kc = b & 63;
    int st = kc >> 4, klocal = kc & 15;
    int p = klocal >> 3, kl7 = klocal & 7;
    int tig = kl7 >> 1, e = kl7 & 1;
    int lane = (n & 7) * 4 + tig, nt = n >> 3;
    uint16_t h, l;
    bfhilo1(v, h, l);
    size_t vi = (size_t)slice * 2560 + (st * 32 + lane) * 20 + nt;
    uint16_t* vb = (uint16_t*)g_vf + vi * 8;
    vb[p * 2 + e] = h;            // hi words .x/.y
    vb[(2 + p) * 2 + e] = l;      // lo words .z/.w

    if (out) out[idx] = v;                      // (B,J,D,1) same linearization
}

// ---------------------------------------------------------------------------
// Kernel D (GEMM2): M=128 x N=80 x K=128 (two 64-batch slices) per block;
// grid (72, 2 slice-pair, 2 n-half) = 288 blocks, 2 blocks/SM, 1 wave.
// W quads prefetched into registers BEFORE the MMA loop; fragment-space
// agreement; g_wa traffic halved vs R16.
// ---------------------------------------------------------------------------
__global__ void __launch_bounds__(256, 2) kernD() {
    extern __shared__ float sm[];
    uint4* bb4 = (uint4*)sm;            // 2816 uint4 = 45056B
    float* sAg = sm + 11264;            // 80 floats: agreement[cl][jl]

    int tid = threadIdx.x;
    int chunk = blockIdx.x, spair = blockIdx.y, nh = blockIdx.z;
    int c0 = chunk * CB2;

    if (tid < 80) sAg[tid] = 0.f;

    // B fragments: 8 k16-steps (s = p*4+st, slice = 2*spair+p), this n-half
#pragma unroll
    for (int i = tid; i < 2560; i += 256) {
        int ntl = i % 10, sl = i / 10;
        int lane = sl & 31, s = sl >> 5;          // s 0..7
        int p = s >> 2, st = s & 3;
        bb4[(s * 32 + lane) * 11 + ntl] =
            g_vf[(size_t)(2 * spair + p) * 2560 + (st * 32 + lane) * 20
                 + nh * 10 + ntl];
    }

    // prefetch agreement W quads (10 per thread) before the MMA loop
    int w = tid >> 5, lane = tid & 31;
    uint4 wq[10];
    {
        const uint4* wap = g_wa + (size_t)chunk * 5120 + w * 640 + nh * 320 + lane;
#pragma unroll
        for (int ntl = 0; ntl < 10; ntl++) wq[ntl] = wap[ntl * 32];
    }
    __syncthreads();

    float d[10][4];
#pragma unroll
    for (int nt = 0; nt < 10; nt++)
#pragma unroll
        for (int q = 0; q < 4; q++) d[nt][q] = 0.f;

    const uint4* aH0 = g_xf2h + ((size_t)chunk * 4 + 2 * spair) * 1024
                     + w * 128 + lane;
    const uint4* aL0 = g_xf2l + ((size_t)chunk * 4 + 2 * spair) * 1024
                     + w * 128 + lane;
#pragma unroll
    for (int s = 0; s < 8; s++) {
        int p = s >> 2, st = s & 3;
        uint4 h = aH0[p * 1024 + st * 32];
        uint4 l = aL0[p * 1024 + st * 32];
        const uint4* bp = bb4 + (s * 32 + lane) * 11;
#pragma unroll
        for (int nt = 0; nt < 10; nt++) {
            uint4 bq = bp[nt];
            mma16(d[nt], h, bq.x, bq.y);   // hi*hi
            mma16(d[nt], h, bq.z, bq.w);   // hi*lo
            mma16(d[nt], l, bq.x, bq.y);   // lo*hi
        }
    }

    // fragment-space agreement: d[ntl] holds G rows (kin16+g, kin16+g+8) for
    // cols n = (nh*10+ntl)*8 + 2tig {,+1}; j = nh*5 + (ntl>>1).
    int g = lane >> 2, tig = lane & 3;
    float ag0[5], ag1[5];
#pragma unroll
    for (int j = 0; j < 5; j++) { ag0[j] = 0.f; ag1[j] = 0.f; }

#pragma unroll
    for (int ntl = 0; ntl < 10; ntl++) {
        float wx = __uint_as_float(wq[ntl].x), wy = __uint_as_float(wq[ntl].y);
        float wz = __uint_as_float(wq[ntl].z), ww = __uint_as_float(wq[ntl].w);
        int jl = ntl >> 1;
        ag0[jl] = fmaf(wx, d[ntl][0], fmaf(wy, d[ntl][1], ag0[jl]));
        ag1[jl] = fmaf(wz, d[ntl][2], fmaf(ww, d[ntl][3], ag1[jl]));
    }
#pragma unroll
    for (int j = 0; j < 5; j++) {
        ag0[j] += __shfl_xor_sync(0xffffffffu, ag0[j], 1, 4);
        ag0[j] += __shfl_xor_sync(0xffffffffu, ag0[j], 2, 4);
        ag1[j] += __shfl_xor_sync(0xffffffffu, ag1[j], 1, 4);
        ag1[j] += __shfl_xor_sync(0xffffffffu, ag1[j], 2, 4);
    }
    if (tig == 0) {
#pragma unroll
        for (int j = 0; j < 5; j++) {
            atomicAdd(&sAg[g * 5 + j], ag0[j]);
            atomicAdd(&sAg[(g + 8) * 5 + j], ag1[j]);
        }
    }
    __syncthreads();

    if (tid < 80) {
        int cl = tid / 5, jl = tid - cl * 5;
        atomicAdd(&g_b[(c0 + cl) * JJ + nh * 5 + jl], sAg[tid]);
    }
}

// ---------------------------------------------------------------------------
// Host launcher (graph-capturable)
// ---------------------------------------------------------------------------
extern "C" void kernel_launch(void* const* d_in, const int* in_sizes, int n_in,
                              void* d_out, int out_size) {
    const float* x = (const float*)d_in[0];
    const float* W = (const float*)d_in[1];
    if (in_sizes[0] != BB * XKC) {   // defensive mapping by element count
        x = (const float*)d_in[1];
        W = (const float*)d_in[0];
    }

    cudaFuncSetAttribute(kernB, cudaFuncAttributeMaxDynamicSharedMemorySize, SMEMB1);
    cudaFuncSetAttribute(kernD, cudaFuncAttributeMaxDynamicSharedMemorySize, SMEMB2);

    void* pb = nullptr;
    cudaGetSymbolAddress(&pb, g_b);
    cudaMemsetAsync(pb, 0, CC * JJ * sizeof(float));   // b_ij = 0 each call

    prepAll<<<792, 256>>>(x, W);                       // all frags, one launch

    dim3 gB(NCHK, 2, 2);    // (72, 2 bhalf, 2 nhalf) = 288 blocks
    dim3 gD(NCH2, 2, 2);    // (72, 2 slice-pairs, 2 nhalf) = 288 blocks
    for (int it = 0; it < 4; it++) {
        kernB<<<gB, 256, SMEMB1>>>();                           // bf16x3 GEMM1
        kernC<<<(BB * JD) / 512, 512>>>(it == 3 ? (float*)d_out : nullptr);
        if (it < 3)                                             // iter-4 agreement dead
            kernD<<<gD, 256, SMEMB2>>>();                       // bf16x3 GEMM2
    }
}